// round 6
// baseline (speedup 1.0000x reference)
#include <cuda_runtime.h>
#include <stdint.h>

// Problem constants (B=1024 batch, V=2 vars, M=256 latent, C=256 categories)
#define B_SZ   1024
#define M_SZ   256
#define C_SZ   256
#define NPAIR  65536          // M*M (k,m) pairs
#define CTAS   512
#define PAIRS_PER_CTA 128     // NPAIR / CTAS
#define THREADS 256
#define NSTAGE 4
#define W1_OFF 16777216LL     // M*M*C = offset of W[1] in floats

// Scratch (static __device__ arrays: no allocation, graph-capture safe)
__device__ float g_acc[B_SZ];   // partial sums, indexed in SORTED order
__device__ int   g_xs0[B_SZ];   // x0 of sorted sample i
__device__ int   g_xs1[B_SZ];   // x1 of sorted sample i (sort key)
__device__ int   g_bidx[B_SZ];  // original b of sorted sample i

// ---------------------------------------------------------------------------
// Kernel 0: counting-sort the 1024 samples by x1 (so that consecutive sorted
// positions share x1 -> near-broadcast smem gathers in kernel 1), and zero the
// accumulators. One CTA, 256 threads, parallel Hillis-Steele scan.
// ---------------------------------------------------------------------------
__global__ void k0_prep(const int* __restrict__ x) {
    __shared__ int hist[256];
    __shared__ int scan[256];
    __shared__ int off[256];
    const int t = threadIdx.x;

    hist[t] = 0;
    __syncthreads();

    int x0v[4], x1v[4];
#pragma unroll
    for (int j = 0; j < 4; j++) {
        int b = t + 256 * j;
        x0v[j] = x[2 * b + 0];
        x1v[j] = x[2 * b + 1];
        atomicAdd(&hist[x1v[j]], 1);
    }
    __syncthreads();

    // inclusive scan of hist
    int h = hist[t];
    scan[t] = h;
    __syncthreads();
#pragma unroll
    for (int d = 1; d < 256; d <<= 1) {
        int add = (t >= d) ? scan[t - d] : 0;
        __syncthreads();
        scan[t] += add;
        __syncthreads();
    }
    off[t] = scan[t] - h;   // exclusive prefix
    __syncthreads();

    // scatter
#pragma unroll
    for (int j = 0; j < 4; j++) {
        int b = t + 256 * j;
        int pos = atomicAdd(&off[x1v[j]], 1);
        g_xs0[pos]  = x0v[j];
        g_xs1[pos]  = x1v[j];
        g_bidx[pos] = b;
    }

    // zero accumulators (graph is replayed: must re-zero every launch)
#pragma unroll
    for (int j = 0; j < 4; j++) g_acc[t + 256 * j] = 0.0f;
}

// ---------------------------------------------------------------------------
// Kernel 1: main accumulation.
//   Each CTA owns 128 consecutive (k,m) pairs and ALL 1024 samples.
//   For each pair: rows W0[k,m,:] and W1[k,m,:] (256 floats each, contiguous)
//   are staged into shared memory through a 4-deep cp.async.cg pipeline
//   (read-once data -> bypass L1). Each thread holds 4 samples (interleaved
//   mapping: sorted positions t, t+256, t+512, t+768 so warp lanes access
//   CONSECUTIVE sorted positions per unrolled step -> x1 nearly constant
//   across the warp -> broadcast-merged LDS for row1).
//   acc[i] += w_sum[k] * row0[x0[i]] * row1[x1[i]],   one atomicAdd per
//   (CTA, sample) at the end.
// ---------------------------------------------------------------------------
__device__ __forceinline__ unsigned smem_u32(const void* p) {
    return (unsigned)__cvta_generic_to_shared(p);
}

__global__ void __launch_bounds__(THREADS, 4)
k1_main(const float* __restrict__ W, const float* __restrict__ w_sum) {
    // stage layout: [row0: 256 floats][row1: 256 floats]
    __shared__ float buf[NSTAGE][2 * C_SZ];
    __shared__ float sw[M_SZ];

    const int t = threadIdx.x;
    sw[t] = w_sum[t];   // cache mixture weights (visible after first barrier)

    int ix0[4], ix1[4];
#pragma unroll
    for (int j = 0; j < 4; j++) {
        ix0[j] = g_xs0[t + 256 * j];
        ix1[j] = g_xs1[t + 256 * j];
    }
    float acc[4] = {0.f, 0.f, 0.f, 0.f};

    const int q0 = blockIdx.x * PAIRS_PER_CTA;             // first pair index
    const float* base0 = W + (long long)q0 * C_SZ;         // W0 rows
    const float* base1 = W + W1_OFF + (long long)q0 * C_SZ; // W1 rows

    // prologue: fill the pipeline
#pragma unroll
    for (int s = 0; s < NSTAGE; s++) {
        if (t < 128) {
            const float* src = (t < 64) ? (base0 + s * C_SZ + t * 4)
                                        : (base1 + s * C_SZ + (t - 64) * 4);
            unsigned dst = smem_u32(&buf[s][(t < 64) ? (t * 4) : (C_SZ + (t - 64) * 4)]);
            asm volatile("cp.async.cg.shared.global [%0], [%1], 16;\n"
                         :: "r"(dst), "l"(src));
        }
        asm volatile("cp.async.commit_group;\n");
    }

    for (int p = 0; p < PAIRS_PER_CTA; p++) {
        // stage p is complete once at most NSTAGE-1 groups remain pending
        // (a commit_group is executed every iteration, possibly empty, so the
        // invariant holds through the tail as well)
        asm volatile("cp.async.wait_group %0;\n" :: "n"(NSTAGE - 1));
        __syncthreads();   // data visible to all threads; prior compute done

        const int st = p & (NSTAGE - 1);
        const float* r0 = &buf[st][0];
        const float* r1 = &buf[st][C_SZ];
        const float wk = sw[(q0 + p) >> 8];   // k = pair / 256

#pragma unroll
        for (int j = 0; j < 4; j++) {
            float a  = r0[ix0[j]];            // random gather  (~3.4 phases)
            float bb = r1[ix1[j]];            // sorted gather  (~broadcast)
            acc[j] = fmaf(a * bb, wk, acc[j]);
        }
        __syncthreads();   // everyone done reading buf[st] before refill

        const int pn = p + NSTAGE;
        if (pn < PAIRS_PER_CTA && t < 128) {
            const float* src = (t < 64) ? (base0 + pn * C_SZ + t * 4)
                                        : (base1 + pn * C_SZ + (t - 64) * 4);
            unsigned dst = smem_u32(&buf[st][(t < 64) ? (t * 4) : (C_SZ + (t - 64) * 4)]);
            asm volatile("cp.async.cg.shared.global [%0], [%1], 16;\n"
                         :: "r"(dst), "l"(src));
        }
        asm volatile("cp.async.commit_group;\n");
    }

#pragma unroll
    for (int j = 0; j < 4; j++)
        atomicAdd(&g_acc[t + 256 * j], acc[j]);
}

// ---------------------------------------------------------------------------
// Kernel 2: out[b] = log(acc), un-permuting from sorted order.
// ---------------------------------------------------------------------------
__global__ void k2_final(float* __restrict__ out) {
    int i = blockIdx.x * blockDim.x + threadIdx.x;
    if (i < B_SZ) out[g_bidx[i]] = logf(g_acc[i]);
}

// ---------------------------------------------------------------------------
// Inputs (metadata order): d_in[0]=x int32 [1024,2], d_in[1]=W fp32 [2,256,256,256],
// d_in[2]=w_sum fp32 [256]. Output: fp32 [1024].
// ---------------------------------------------------------------------------
extern "C" void kernel_launch(void* const* d_in, const int* in_sizes, int n_in,
                              void* d_out, int out_size) {
    (void)in_sizes; (void)n_in; (void)out_size;
    const int*   x     = (const int*)d_in[0];
    const float* W     = (const float*)d_in[1];
    const float* w_sum = (const float*)d_in[2];
    float*       out   = (float*)d_out;

    k0_prep<<<1, 256>>>(x);
    k1_main<<<CTAS, THREADS>>>(W, w_sum);
    k2_final<<<4, 256>>>(out);
}

// round 7
// speedup vs baseline: 1.1705x; 1.1705x over previous
#include <cuda_runtime.h>
#include <stdint.h>

// Problem constants (B=1024 batch, V=2 vars, M=256 latent, C=256 categories)
#define B_SZ   1024
#define M_SZ   256
#define C_SZ   256
#define NPAIR  65536          // M*M (k,m) pairs
#define CTAS   512
#define PAIRS_PER_CTA 128     // NPAIR / CTAS  (all within ONE k: k = pair>>8)
#define NITER  64             // 2 pairs per iteration
#define THREADS 256
#define NSTAGE 4
#define W1_OFF 16777216LL     // M*M*C = offset of W[1] in floats

// Scratch (static __device__ arrays: no allocation, graph-capture safe)
__device__ float g_acc[B_SZ];   // partial sums, indexed in SORTED order
__device__ int   g_xs0[B_SZ];   // x0 of sorted sample i
__device__ int   g_xs1[B_SZ];   // x1 of sorted sample i (sort key)
__device__ int   g_bidx[B_SZ];  // original b of sorted sample i

// ---------------------------------------------------------------------------
// Kernel 0: counting-sort the 1024 samples by x1 (consecutive sorted positions
// share x1 -> near-broadcast smem gathers in kernel 1) and zero accumulators.
// 1 CTA x 1024 threads; warp-shuffle scan (4 barriers total, vs 16 before).
// ---------------------------------------------------------------------------
__global__ void k0_prep(const int* __restrict__ x) {
    __shared__ int hist[256];
    __shared__ int wsum[8];
    __shared__ int off[256];
    const int t    = threadIdx.x;       // 0..1023
    const int lane = t & 31;

    if (t < 256) hist[t] = 0;
    __syncthreads();

    const int x0 = x[2 * t + 0];
    const int x1 = x[2 * t + 1];
    atomicAdd(&hist[x1], 1);
    g_acc[t] = 0.0f;                    // re-zero every graph replay
    __syncthreads();

    int v = 0, h = 0;
    if (t < 256) {
        h = hist[t];
        v = h;
        // intra-warp inclusive scan (5 shfl steps, no barriers)
#pragma unroll
        for (int d = 1; d < 32; d <<= 1) {
            int n = __shfl_up_sync(0xffffffffu, v, d);
            if (lane >= d) v += n;
        }
        if (lane == 31) wsum[t >> 5] = v;
    }
    __syncthreads();
    if (t == 0) {                        // serial exclusive scan of 8 warp sums
        int s = 0;
#pragma unroll
        for (int i = 0; i < 8; i++) { int tmp = wsum[i]; wsum[i] = s; s += tmp; }
    }
    __syncthreads();
    if (t < 256) off[t] = (v - h) + wsum[t >> 5];   // exclusive prefix
    __syncthreads();

    const int pos = atomicAdd(&off[x1], 1);
    g_xs0[pos]  = x0;
    g_xs1[pos]  = x1;
    g_bidx[pos] = t;
}

// ---------------------------------------------------------------------------
// Kernel 1: main accumulation.
//   Each CTA owns 128 consecutive (k,m) pairs (one k!) and ALL 1024 samples.
//   Two pairs per pipeline stage (4KB: [row0_A|row0_B|row1_A|row1_B]), 4-deep
//   cp.async.cg pipeline, ONE __syncthreads per iteration:
//     iter i: wait_group(2); sync; refill stage (i+3)&3 (==(i-1)&3, consumed
//     at iter i-1, safe after this barrier); commit; compute stage i&3.
//   w_sum[k] is constant per CTA -> applied once in the epilogue; inner update
//   is a single fmaf per (pair, sample).
// ---------------------------------------------------------------------------
__device__ __forceinline__ unsigned smem_u32(const void* p) {
    return (unsigned)__cvta_generic_to_shared(p);
}

__global__ void __launch_bounds__(THREADS, 4)
k1_main(const float* __restrict__ W, const float* __restrict__ w_sum) {
    // stage layout: [0:256) row0 of pair 2i, [256:512) row0 of pair 2i+1,
    //               [512:768) row1 of pair 2i, [768:1024) row1 of pair 2i+1
    __shared__ float buf[NSTAGE][4 * C_SZ];

    const int t = threadIdx.x;
    const int q0 = blockIdx.x * PAIRS_PER_CTA;
    const float wk = __ldg(w_sum + (q0 >> 8));              // k constant per CTA
    const float* base0 = W + (long long)q0 * C_SZ;          // W0 rows
    const float* base1 = W + W1_OFF + (long long)q0 * C_SZ; // W1 rows

    int ix0[4], ix1[4];
#pragma unroll
    for (int j = 0; j < 4; j++) {
        ix0[j] = g_xs0[t + 256 * j];
        ix1[j] = g_xs1[t + 256 * j];
    }
    float acc[4] = {0.f, 0.f, 0.f, 0.f};

    // issue one 16B cp.async per thread for iteration `it` into stage `s`:
    // t<128 covers the 512-float W0 span of pairs (2it, 2it+1), t>=128 the W1 span.
#define ISSUE(s, it)                                                          \
    do {                                                                      \
        const float* _src = (t < 128) ? (base0 + (it) * 512 + t * 4)          \
                                      : (base1 + (it) * 512 + (t - 128) * 4); \
        unsigned _dst = smem_u32(&buf[s][(t < 128) ? (t * 4)                  \
                                                   : (512 + (t - 128) * 4)]); \
        asm volatile("cp.async.cg.shared.global [%0], [%1], 16;\n"            \
                     :: "r"(_dst), "l"(_src));                                \
    } while (0)

    // prologue: stages 0,1,2 for iterations 0,1,2 (3 committed groups)
#pragma unroll
    for (int s = 0; s < NSTAGE - 1; s++) {
        ISSUE(s, s);
        asm volatile("cp.async.commit_group;\n");
    }

    for (int i = 0; i < NITER; i++) {
        asm volatile("cp.async.wait_group %0;\n" :: "n"(NSTAGE - 2));
        __syncthreads();   // stage i&3 visible to all; stage (i-1)&3 fully consumed

        const int ip = i + NSTAGE - 1;
        if (ip < NITER) ISSUE(ip & (NSTAGE - 1), ip);
        asm volatile("cp.async.commit_group;\n");   // (possibly empty) keeps count

        const float* s0 = buf[i & (NSTAGE - 1)];
#pragma unroll
        for (int j = 0; j < 4; j++) {
            float a0 = s0[ix0[j]];          // pair A row0 (random, ~3.4 phases)
            float b0 = s0[512 + ix1[j]];    // pair A row1 (sorted, ~broadcast)
            float a1 = s0[256 + ix0[j]];    // pair B row0
            float b1 = s0[768 + ix1[j]];    // pair B row1
            acc[j] = fmaf(a0, b0, acc[j]);
            acc[j] = fmaf(a1, b1, acc[j]);
        }
    }
#undef ISSUE

#pragma unroll
    for (int j = 0; j < 4; j++)
        atomicAdd(&g_acc[t + 256 * j], acc[j] * wk);
}

// ---------------------------------------------------------------------------
// Kernel 2: out[b] = log(acc), un-permuting from sorted order.
// ---------------------------------------------------------------------------
__global__ void k2_final(float* __restrict__ out) {
    int i = blockIdx.x * blockDim.x + threadIdx.x;
    if (i < B_SZ) out[g_bidx[i]] = logf(g_acc[i]);
}

// ---------------------------------------------------------------------------
// Inputs (metadata order): d_in[0]=x int32 [1024,2], d_in[1]=W fp32 [2,256,256,256],
// d_in[2]=w_sum fp32 [256]. Output: fp32 [1024].
// ---------------------------------------------------------------------------
extern "C" void kernel_launch(void* const* d_in, const int* in_sizes, int n_in,
                              void* d_out, int out_size) {
    (void)in_sizes; (void)n_in; (void)out_size;
    const int*   x     = (const int*)d_in[0];
    const float* W     = (const float*)d_in[1];
    const float* w_sum = (const float*)d_in[2];
    float*       out   = (float*)d_out;

    k0_prep<<<1, 1024>>>(x);
    k1_main<<<CTAS, THREADS>>>(W, w_sum);
    k2_final<<<4, 256>>>(out);
}